// round 1
// baseline (speedup 1.0000x reference)
#include <cuda_runtime.h>
#include <math.h>

#define N_ROWS  65536
#define CDIM    256
#define KCODES  1024
#define HW      4096
#define BM      128
#define BN      128
#define BKc     16
#define NTHREADS 256

// output layout: [loss(1), z_q_out(16777216), idx(65536), perplexity(1)]
#define OFF_ZQ   1
#define OFF_IDX  (1 + 16777216)
#define OFF_PERP (1 + 16777216 + 65536)

__device__ float  g_ee[KCODES];
__device__ int    g_idx[N_ROWS];
__device__ int    g_cnt[KCODES];
__device__ double g_loss;

// ---------------------------------------------------------------------------
// K1: ee[k] = sum_c e[k][c]^2 (double accum), zero counts + loss
// grid 128 x 256 threads (8 warps -> 8 rows per block)
// ---------------------------------------------------------------------------
__global__ void k_prep(const float* __restrict__ e) {
    int tid = threadIdx.x, bid = blockIdx.x;
    int warp = tid >> 5, lane = tid & 31;
    int row = bid * 8 + warp;
    const float* er = e + (size_t)row * CDIM;
    double s = 0.0;
    #pragma unroll
    for (int q = 0; q < 8; q++) {
        float v = er[lane + 32 * q];
        s += (double)v * (double)v;
    }
    #pragma unroll
    for (int off = 16; off; off >>= 1)
        s += __shfl_down_sync(0xffffffffu, s, off);
    if (lane == 0) g_ee[row] = (float)s;

    int gt = bid * NTHREADS + tid;
    if (gt < KCODES) g_cnt[gt] = 0;
    if (gt == 0) g_loss = 0.0;
}

// ---------------------------------------------------------------------------
// K2: fused GEMM + argmin. Each block: 128 rows x all 1024 codes.
// d[n][k] = zz[n] + ee[k] - 2 * dot(zf[n], e[k]), argmin_k with first-index
// tie-break (matches jnp.argmin).
// ---------------------------------------------------------------------------
__global__ __launch_bounds__(NTHREADS, 2)
void k_main(const float* __restrict__ z, const float* __restrict__ e,
            float* __restrict__ out_idx) {
    __shared__ __align__(16) float zs[BKc][BM];
    __shared__ __align__(16) float es[BKc][BN];
    __shared__ float  ee_s[KCODES];
    __shared__ float  zz_s[BM];
    __shared__ double zd[NTHREADS];
    __shared__ float  sval[BM][16];
    __shared__ int    sidx[BM][16];

    const int tid = threadIdx.x;
    const int n0  = blockIdx.x * BM;
    const int b   = n0 >> 12;          // n0 / 4096
    const int hw0 = n0 & 4095;
    const float* zb = z + (size_t)b * (CDIM * HW) + hw0;

    // ---- zz for this block's 128 rows, double accumulation ----
    {
        int m = tid & 127, cg = tid >> 7;
        double s = 0.0;
        for (int cc = 0; cc < 128; cc++) {
            float v = zb[(size_t)(cg + 2 * cc) * HW + m];
            s += (double)v * (double)v;
        }
        zd[tid] = s;
    }
    for (int i = tid; i < KCODES; i += NTHREADS) ee_s[i] = g_ee[i];
    __syncthreads();
    if (tid < BM) zz_s[tid] = (float)(zd[tid] + zd[tid + BM]);
    __syncthreads();

    const int trow = tid >> 4;   // 0..15 -> rows trow*8 .. trow*8+7
    const int tcol = tid & 15;   // 0..15 -> codes tcol*8 .. tcol*8+7 (per tile)

    float bestv[8];
    int   besti[8];
    #pragma unroll
    for (int i = 0; i < 8; i++) { bestv[i] = INFINITY; besti[i] = 0; }

    for (int c0 = 0; c0 < KCODES; c0 += BN) {
        float acc[8][8];
        #pragma unroll
        for (int i = 0; i < 8; i++)
            #pragma unroll
            for (int j = 0; j < 8; j++) acc[i][j] = 0.0f;

        for (int kt = 0; kt < CDIM; kt += BKc) {
            // load z tile: zs[c][m] = zf[n0+m][kt+c]  (coalesced: m is fast axis)
            #pragma unroll
            for (int it = 0; it < 2; it++) {
                int u  = tid + it * NTHREADS;         // 0..511
                int c  = u >> 5;                      // 0..15
                int m4 = (u & 31) << 2;               // 0..124
                float4 v = *(const float4*)(zb + (size_t)(kt + c) * HW + m4);
                *(float4*)&zs[c][m4] = v;
            }
            // load e tile transposed: es[c][n] = e[c0+n][kt+c]
            #pragma unroll
            for (int it = 0; it < 2; it++) {
                int u   = tid + it * NTHREADS;        // 0..511
                int n   = u >> 2;                     // 0..127
                int cq4 = (u & 3) << 2;               // 0,4,8,12
                float4 v = *(const float4*)(e + (size_t)(c0 + n) * CDIM + kt + cq4);
                es[cq4 + 0][n] = v.x;
                es[cq4 + 1][n] = v.y;
                es[cq4 + 2][n] = v.z;
                es[cq4 + 3][n] = v.w;
            }
            __syncthreads();

            #pragma unroll
            for (int k = 0; k < BKc; k++) {
                float4 a0 = *(const float4*)&zs[k][trow * 8];
                float4 a1 = *(const float4*)&zs[k][trow * 8 + 4];
                float4 b0 = *(const float4*)&es[k][tcol * 8];
                float4 b1 = *(const float4*)&es[k][tcol * 8 + 4];
                float av[8] = {a0.x, a0.y, a0.z, a0.w, a1.x, a1.y, a1.z, a1.w};
                float bv[8] = {b0.x, b0.y, b0.z, b0.w, b1.x, b1.y, b1.z, b1.w};
                #pragma unroll
                for (int i = 0; i < 8; i++)
                    #pragma unroll
                    for (int j = 0; j < 8; j++)
                        acc[i][j] += av[i] * bv[j];
            }
            __syncthreads();
        }

        // epilogue: d = (zz + ee) - 2*dot, explicit rounding to match JAX
        #pragma unroll
        for (int i = 0; i < 8; i++) {
            float zr = zz_s[trow * 8 + i];
            #pragma unroll
            for (int j = 0; j < 8; j++) {
                int code = c0 + tcol * 8 + j;
                float t = __fadd_rn(zr, ee_s[code]);
                float d = __fsub_rn(t, __fmul_rn(2.0f, acc[i][j]));
                if (d < bestv[i] || (d == bestv[i] && code < besti[i])) {
                    bestv[i] = d;
                    besti[i] = code;
                }
            }
        }
    }

    // cross-thread argmin reduce (16 code-column threads per row)
    #pragma unroll
    for (int i = 0; i < 8; i++) {
        sval[trow * 8 + i][tcol] = bestv[i];
        sidx[trow * 8 + i][tcol] = besti[i];
    }
    __syncthreads();
    if (tid < BM) {
        float bv = sval[tid][0];
        int   bi = sidx[tid][0];
        #pragma unroll
        for (int tc = 1; tc < 16; tc++) {
            float v  = sval[tid][tc];
            int   ii = sidx[tid][tc];
            if (v < bv || (v == bv && ii < bi)) { bv = v; bi = ii; }
        }
        int n = n0 + tid;
        g_idx[n]   = bi;
        out_idx[n] = (float)bi;
        atomicAdd(&g_cnt[bi], 1);
    }
}

// ---------------------------------------------------------------------------
// K3: codebook scatter to [B,C,H,W] layout + loss accumulation (double)
// out = fl(zp + fl(zq - zp))  (straight-through, elementwise rounding as JAX)
// ---------------------------------------------------------------------------
__global__ void k_scatter(const float* __restrict__ z, const float* __restrict__ e,
                          float* __restrict__ out_zq) {
    __shared__ int    sid[BM];
    __shared__ double sred[NTHREADS];
    const int tid = threadIdx.x;
    const int n0  = blockIdx.x * BM;
    const int b   = n0 >> 12;
    const int hw0 = n0 & 4095;
    if (tid < BM) sid[tid] = g_idx[n0 + tid];
    __syncthreads();

    const int m = tid & 127, cg = tid >> 7;
    const float* zbase = z      + (size_t)b * (CDIM * HW) + hw0 + m;
    float*       obase = out_zq + (size_t)b * (CDIM * HW) + hw0 + m;
    const float* erow  = e + (size_t)sid[m] * CDIM;

    double s = 0.0;
    for (int cc = 0; cc < 128; cc++) {
        int c = cg + 2 * cc;
        float zv = zbase[(size_t)c * HW];
        float qv = erow[c];
        float df = __fsub_rn(qv, zv);
        obase[(size_t)c * HW] = __fadd_rn(zv, df);   // straight-through value
        s += (double)df * (double)df;
    }
    sred[tid] = s;
    __syncthreads();
    #pragma unroll
    for (int off = 128; off; off >>= 1) {
        if (tid < off) sred[tid] += sred[tid + off];
        __syncthreads();
    }
    if (tid == 0) atomicAdd(&g_loss, sred[0]);
}

// ---------------------------------------------------------------------------
// K4: loss + perplexity finalize (1 block, 1024 threads)
// ---------------------------------------------------------------------------
__global__ void k_final(float* __restrict__ out) {
    __shared__ float sred[KCODES];
    int t = threadIdx.x;
    float p = (float)g_cnt[t] * (1.0f / 65536.0f);
    sred[t] = p * logf(p + 1e-10f);
    __syncthreads();
    #pragma unroll
    for (int off = 512; off; off >>= 1) {
        if (t < off) sred[t] += sred[t + off];
        __syncthreads();
    }
    if (t == 0) {
        out[0]        = (float)(g_loss * (1.25 / 16777216.0));
        out[OFF_PERP] = expf(-sred[0]);
    }
}

// ---------------------------------------------------------------------------
extern "C" void kernel_launch(void* const* d_in, const int* in_sizes, int n_in,
                              void* d_out, int out_size) {
    // z is the larger input (16.7M elems), embed_w the smaller (262144)
    const float* z = (const float*)d_in[0];
    const float* e = (const float*)d_in[1];
    if (n_in >= 2 && in_sizes[0] < in_sizes[1]) {
        z = (const float*)d_in[1];
        e = (const float*)d_in[0];
    }
    float* out = (float*)d_out;

    k_prep   <<<KCODES / 8, NTHREADS>>>(e);
    k_main   <<<N_ROWS / BM, NTHREADS>>>(z, e, out + OFF_IDX);
    k_scatter<<<N_ROWS / BM, NTHREADS>>>(z, e, out + OFF_ZQ);
    k_final  <<<1, KCODES>>>(out);
}

// round 2
// speedup vs baseline: 1.0010x; 1.0010x over previous
#include <cuda_runtime.h>
#include <math.h>

#define N_ROWS  65536
#define CDIM    256
#define KCODES  1024
#define HW      4096
#define BM      128
#define BN      128
#define BKc     16
#define NTHREADS 256

// output layout: [loss(1), z_q_out(16777216), idx(65536), perplexity(1)]
#define OFF_ZQ   1
#define OFF_IDX  (1 + 16777216)
#define OFF_PERP (1 + 16777216 + 65536)

__device__ float  g_ee[KCODES];
__device__ int    g_idx[N_ROWS];
__device__ int    g_cnt[KCODES];
__device__ double g_loss;

// ---------------------------------------------------------------------------
// K1: ee[k] = sum_c e[k][c]^2 (double accum), zero counts + loss
// grid 128 x 256 threads (8 warps -> 8 rows per block)
// ---------------------------------------------------------------------------
__global__ void k_prep(const float* __restrict__ e) {
    int tid = threadIdx.x, bid = blockIdx.x;
    int warp = tid >> 5, lane = tid & 31;
    int row = bid * 8 + warp;
    const float* er = e + (size_t)row * CDIM;
    double s = 0.0;
    #pragma unroll
    for (int q = 0; q < 8; q++) {
        float v = er[lane + 32 * q];
        s += (double)v * (double)v;
    }
    #pragma unroll
    for (int off = 16; off; off >>= 1)
        s += __shfl_down_sync(0xffffffffu, s, off);
    if (lane == 0) g_ee[row] = (float)s;

    int gt = bid * NTHREADS + tid;
    if (gt < KCODES) g_cnt[gt] = 0;
    if (gt == 0) g_loss = 0.0;
}

// ---------------------------------------------------------------------------
// K2: fused GEMM + argmin. Each block: 128 rows x all 1024 codes.
// d[n][k] = zz[n] + ee[k] - 2 * dot(zf[n], e[k]), argmin_k with first-index
// tie-break (matches jnp.argmin).
// ---------------------------------------------------------------------------
__global__ __launch_bounds__(NTHREADS, 2)
void k_main(const float* __restrict__ z, const float* __restrict__ e,
            float* __restrict__ out_idx) {
    __shared__ __align__(16) float zs[BKc][BM];
    __shared__ __align__(16) float es[BKc][BN];
    __shared__ float  ee_s[KCODES];
    __shared__ float  zz_s[BM];
    __shared__ double zd[NTHREADS];
    __shared__ float  sval[BM][16];
    __shared__ int    sidx[BM][16];

    const int tid = threadIdx.x;
    const int n0  = blockIdx.x * BM;
    const int b   = n0 >> 12;          // n0 / 4096
    const int hw0 = n0 & 4095;
    const float* zb = z + (size_t)b * (CDIM * HW) + hw0;

    // ---- zz for this block's 128 rows, double accumulation ----
    {
        int m = tid & 127, cg = tid >> 7;
        double s = 0.0;
        for (int cc = 0; cc < 128; cc++) {
            float v = zb[(size_t)(cg + 2 * cc) * HW + m];
            s += (double)v * (double)v;
        }
        zd[tid] = s;
    }
    for (int i = tid; i < KCODES; i += NTHREADS) ee_s[i] = g_ee[i];
    __syncthreads();
    if (tid < BM) zz_s[tid] = (float)(zd[tid] + zd[tid + BM]);
    __syncthreads();

    const int trow = tid >> 4;   // 0..15 -> rows trow*8 .. trow*8+7
    const int tcol = tid & 15;   // 0..15 -> codes tcol*8 .. tcol*8+7 (per tile)

    float bestv[8];
    int   besti[8];
    #pragma unroll
    for (int i = 0; i < 8; i++) { bestv[i] = INFINITY; besti[i] = 0; }

    for (int c0 = 0; c0 < KCODES; c0 += BN) {
        float acc[8][8];
        #pragma unroll
        for (int i = 0; i < 8; i++)
            #pragma unroll
            for (int j = 0; j < 8; j++) acc[i][j] = 0.0f;

        for (int kt = 0; kt < CDIM; kt += BKc) {
            // load z tile: zs[c][m] = zf[n0+m][kt+c]  (coalesced: m is fast axis)
            #pragma unroll
            for (int it = 0; it < 2; it++) {
                int u  = tid + it * NTHREADS;         // 0..511
                int c  = u >> 5;                      // 0..15
                int m4 = (u & 31) << 2;               // 0..124
                float4 v = *(const float4*)(zb + (size_t)(kt + c) * HW + m4);
                *(float4*)&zs[c][m4] = v;
            }
            // load e tile transposed: es[c][n] = e[c0+n][kt+c]
            #pragma unroll
            for (int it = 0; it < 2; it++) {
                int u   = tid + it * NTHREADS;        // 0..511
                int n   = u >> 2;                     // 0..127
                int cq4 = (u & 3) << 2;               // 0,4,8,12
                float4 v = *(const float4*)(e + (size_t)(c0 + n) * CDIM + kt + cq4);
                es[cq4 + 0][n] = v.x;
                es[cq4 + 1][n] = v.y;
                es[cq4 + 2][n] = v.z;
                es[cq4 + 3][n] = v.w;
            }
            __syncthreads();

            #pragma unroll
            for (int k = 0; k < BKc; k++) {
                float4 a0 = *(const float4*)&zs[k][trow * 8];
                float4 a1 = *(const float4*)&zs[k][trow * 8 + 4];
                float4 b0 = *(const float4*)&es[k][tcol * 8];
                float4 b1 = *(const float4*)&es[k][tcol * 8 + 4];
                float av[8] = {a0.x, a0.y, a0.z, a0.w, a1.x, a1.y, a1.z, a1.w};
                float bv[8] = {b0.x, b0.y, b0.z, b0.w, b1.x, b1.y, b1.z, b1.w};
                #pragma unroll
                for (int i = 0; i < 8; i++)
                    #pragma unroll
                    for (int j = 0; j < 8; j++)
                        acc[i][j] += av[i] * bv[j];
            }
            __syncthreads();
        }

        // epilogue: d = (zz + ee) - 2*dot, explicit rounding to match JAX
        #pragma unroll
        for (int i = 0; i < 8; i++) {
            float zr = zz_s[trow * 8 + i];
            #pragma unroll
            for (int j = 0; j < 8; j++) {
                int code = c0 + tcol * 8 + j;
                float t = __fadd_rn(zr, ee_s[code]);
                float d = __fsub_rn(t, __fmul_rn(2.0f, acc[i][j]));
                if (d < bestv[i] || (d == bestv[i] && code < besti[i])) {
                    bestv[i] = d;
                    besti[i] = code;
                }
            }
        }
    }

    // cross-thread argmin reduce (16 code-column threads per row)
    #pragma unroll
    for (int i = 0; i < 8; i++) {
        sval[trow * 8 + i][tcol] = bestv[i];
        sidx[trow * 8 + i][tcol] = besti[i];
    }
    __syncthreads();
    if (tid < BM) {
        float bv = sval[tid][0];
        int   bi = sidx[tid][0];
        #pragma unroll
        for (int tc = 1; tc < 16; tc++) {
            float v  = sval[tid][tc];
            int   ii = sidx[tid][tc];
            if (v < bv || (v == bv && ii < bi)) { bv = v; bi = ii; }
        }
        int n = n0 + tid;
        g_idx[n]   = bi;
        out_idx[n] = (float)bi;
        atomicAdd(&g_cnt[bi], 1);
    }
}

// ---------------------------------------------------------------------------
// K3: codebook scatter to [B,C,H,W] layout + loss accumulation (double)
// out = fl(zp + fl(zq - zp))  (straight-through, elementwise rounding as JAX)
// ---------------------------------------------------------------------------
__global__ void k_scatter(const float* __restrict__ z, const float* __restrict__ e,
                          float* __restrict__ out_zq) {
    __shared__ int    sid[BM];
    __shared__ double sred[NTHREADS];
    const int tid = threadIdx.x;
    const int n0  = blockIdx.x * BM;
    const int b   = n0 >> 12;
    const int hw0 = n0 & 4095;
    if (tid < BM) sid[tid] = g_idx[n0 + tid];
    __syncthreads();

    const int m = tid & 127, cg = tid >> 7;
    const float* zbase = z      + (size_t)b * (CDIM * HW) + hw0 + m;
    float*       obase = out_zq + (size_t)b * (CDIM * HW) + hw0 + m;
    const float* erow  = e + (size_t)sid[m] * CDIM;

    double s = 0.0;
    for (int cc = 0; cc < 128; cc++) {
        int c = cg + 2 * cc;
        float zv = zbase[(size_t)c * HW];
        float qv = erow[c];
        float df = __fsub_rn(qv, zv);
        obase[(size_t)c * HW] = __fadd_rn(zv, df);   // straight-through value
        s += (double)df * (double)df;
    }
    sred[tid] = s;
    __syncthreads();
    #pragma unroll
    for (int off = 128; off; off >>= 1) {
        if (tid < off) sred[tid] += sred[tid + off];
        __syncthreads();
    }
    if (tid == 0) atomicAdd(&g_loss, sred[0]);
}

// ---------------------------------------------------------------------------
// K4: loss + perplexity finalize (1 block, 1024 threads)
// ---------------------------------------------------------------------------
__global__ void k_final(float* __restrict__ out) {
    __shared__ float sred[KCODES];
    int t = threadIdx.x;
    float p = (float)g_cnt[t] * (1.0f / 65536.0f);
    sred[t] = p * logf(p + 1e-10f);
    __syncthreads();
    #pragma unroll
    for (int off = 512; off; off >>= 1) {
        if (t < off) sred[t] += sred[t + off];
        __syncthreads();
    }
    if (t == 0) {
        out[0]        = (float)(g_loss * (1.25 / 16777216.0));
        out[OFF_PERP] = expf(-sred[0]);
    }
}

// ---------------------------------------------------------------------------
extern "C" void kernel_launch(void* const* d_in, const int* in_sizes, int n_in,
                              void* d_out, int out_size) {
    // z is the larger input (16.7M elems), embed_w the smaller (262144)
    const float* z = (const float*)d_in[0];
    const float* e = (const float*)d_in[1];
    if (n_in >= 2 && in_sizes[0] < in_sizes[1]) {
        z = (const float*)d_in[1];
        e = (const float*)d_in[0];
    }
    float* out = (float*)d_out;

    k_prep   <<<KCODES / 8, NTHREADS>>>(e);
    k_main   <<<N_ROWS / BM, NTHREADS>>>(z, e, out + OFF_IDX);
    k_scatter<<<N_ROWS / BM, NTHREADS>>>(z, e, out + OFF_ZQ);
    k_final  <<<1, KCODES>>>(out);
}

// round 4
// speedup vs baseline: 1.9291x; 1.9272x over previous
#include <cuda_runtime.h>
#include <cuda_fp16.h>
#include <math.h>
#include <stdint.h>

#define N_ROWS  65536
#define CDIM    256
#define KCODES  1024
#define HW      4096

#define OFF_ZQ   1
#define OFF_IDX  (1 + 16777216)
#define OFF_PERP (1 + 16777216 + 65536)

#define GT 256            // gemm threads
#define BM 128            // rows per CTA
#define BNC 64            // codes per chunk
#define NCHUNKS 16

// fp16 operand mirrors
__device__ __align__(16) __half g_zf16[(size_t)N_ROWS * CDIM];
__device__ __align__(16) __half g_ef16[(size_t)KCODES * CDIM];
__device__ float  g_zz[N_ROWS];
__device__ float  g_ee[KCODES];
__device__ int    g_idx[N_ROWS];
__device__ int    g_cnt[KCODES];
__device__ double g_loss;

// ---------------- PTX helpers (baseline ISA only) ----------------
__device__ __forceinline__ uint32_t smem_u32(const void* p) {
    uint32_t a;
    asm("{ .reg .u64 t; cvta.to.shared.u64 t, %1; cvt.u32.u64 %0, t; }" : "=r"(a) : "l"(p));
    return a;
}
__device__ __forceinline__ void cp16(uint32_t dst, const void* src) {
    asm volatile("cp.async.cg.shared.global [%0], [%1], 16;" :: "r"(dst), "l"(src));
}
#define CP_COMMIT() asm volatile("cp.async.commit_group;" ::: "memory")
#define CP_WAIT0()  asm volatile("cp.async.wait_group 0;" ::: "memory")

__device__ __forceinline__ void ldsm4(uint32_t& r0, uint32_t& r1, uint32_t& r2,
                                      uint32_t& r3, uint32_t addr) {
    asm volatile("ldmatrix.sync.aligned.m8n8.x4.shared.b16 {%0,%1,%2,%3}, [%4];"
                 : "=r"(r0), "=r"(r1), "=r"(r2), "=r"(r3) : "r"(addr));
}
__device__ __forceinline__ void mma16816(float* c, uint32_t a0, uint32_t a1,
                                         uint32_t a2, uint32_t a3,
                                         uint32_t b0, uint32_t b1) {
    asm volatile(
        "mma.sync.aligned.m16n8k16.row.col.f32.f16.f16.f32 "
        "{%0,%1,%2,%3}, {%4,%5,%6,%7}, {%8,%9}, {%0,%1,%2,%3};"
        : "+f"(c[0]), "+f"(c[1]), "+f"(c[2]), "+f"(c[3])
        : "r"(a0), "r"(a1), "r"(a2), "r"(a3), "r"(b0), "r"(b1));
}

// ---------------------------------------------------------------------------
// K1: e -> fp16 mirror + ee (double), zero counters. grid 4 x 256.
// ---------------------------------------------------------------------------
__global__ void k_prep(const float* __restrict__ e) {
    const int code = blockIdx.x * 256 + threadIdx.x;
    const float* er = e + (size_t)code * CDIM;
    __half* hr = g_ef16 + (size_t)code * CDIM;
    double s = 0.0;
    for (int c8 = 0; c8 < CDIM; c8 += 8) {
        float v[8];
        *(float4*)&v[0] = *(const float4*)(er + c8);
        *(float4*)&v[4] = *(const float4*)(er + c8 + 4);
        __half2 h[4];
        #pragma unroll
        for (int i = 0; i < 4; i++) h[i] = __floats2half2_rn(v[2*i], v[2*i+1]);
        *(uint4*)(hr + c8) = *(uint4*)h;
        #pragma unroll
        for (int i = 0; i < 8; i++) s += (double)v[i] * (double)v[i];
    }
    g_ee[code]  = (float)s;
    g_cnt[code] = 0;
    if (code == 0) g_loss = 0.0;
}

// ---------------------------------------------------------------------------
// K2: z -> fp16 row-major [n][c] + zz. grid 256 x 256, thread = 1 row.
// Reads coalesced across threads (consecutive hw), writes 16B per thread.
// ---------------------------------------------------------------------------
__global__ __launch_bounds__(256) void k_conv(const float* __restrict__ z) {
    const int n = blockIdx.x * 256 + threadIdx.x;
    const int b = n >> 12, hw = n & 4095;
    const float* zb = z + (size_t)b * (CDIM * HW) + hw;
    __half* hr = g_zf16 + (size_t)n * CDIM;
    double s = 0.0;
    for (int c8 = 0; c8 < CDIM; c8 += 8) {
        float v[8];
        #pragma unroll
        for (int i = 0; i < 8; i++) v[i] = zb[(size_t)(c8 + i) * HW];
        __half2 h[4];
        #pragma unroll
        for (int i = 0; i < 4; i++) h[i] = __floats2half2_rn(v[2*i], v[2*i+1]);
        *(uint4*)(hr + c8) = *(uint4*)h;
        #pragma unroll
        for (int i = 0; i < 8; i++) s += (double)v[i] * (double)v[i];
    }
    g_zz[n] = (float)s;
}

// ---------------------------------------------------------------------------
// top-2 helpers
// ---------------------------------------------------------------------------
#define UPD(v1, i1, v2, i2, d, cd) do { \
    if ((d) < (v1) || ((d) == (v1) && (cd) < (i1))) { \
        (v2) = (v1); (i2) = (i1); (v1) = (d); (i1) = (cd); \
    } else if ((d) < (v2) || ((d) == (v2) && (cd) < (i2))) { \
        (v2) = (d); (i2) = (cd); \
    } } while (0)

__device__ __forceinline__ void merge_quad(float& v1, int& i1, float& v2, int& i2) {
    #pragma unroll
    for (int m = 1; m <= 2; m <<= 1) {
        float w1 = __shfl_xor_sync(0xffffffffu, v1, m);
        int   j1 = __shfl_xor_sync(0xffffffffu, i1, m);
        float w2 = __shfl_xor_sync(0xffffffffu, v2, m);
        int   j2 = __shfl_xor_sync(0xffffffffu, i2, m);
        if (w1 < v1 || (w1 == v1 && j1 < i1)) {
            v2 = v1; i2 = i1; v1 = w1; i1 = j1;
            if (w2 < v2 || (w2 == v2 && j2 < i2)) { v2 = w2; i2 = j2; }
        } else if (w1 < v2 || (w1 == v2 && j1 < i2)) {
            v2 = w1; i2 = j1;
        }
    }
}

__device__ __forceinline__ void finalize_row(int row, float v1, int i1,
                                             float v2, int i2, float zzv,
                                             const float* __restrict__ z,
                                             const float* __restrict__ e,
                                             float* __restrict__ out_idx) {
    if (v2 - v1 < 1e-4f) {
        // exact fp32 recheck, same op/rounding sequence as the verified R1 path
        const float* zr = z + (size_t)(row >> 12) * (CDIM * HW) + (row & 4095);
        const float* e1 = e + (size_t)i1 * CDIM;
        const float* e2 = e + (size_t)i2 * CDIM;
        float a1 = 0.0f, a2 = 0.0f;
        for (int c = 0; c < CDIM; c++) {
            float zv = zr[(size_t)c * HW];
            a1 = fmaf(zv, e1[c], a1);
            a2 = fmaf(zv, e2[c], a2);
        }
        float d1 = __fsub_rn(__fadd_rn(zzv, g_ee[i1]), __fmul_rn(2.0f, a1));
        float d2 = __fsub_rn(__fadd_rn(zzv, g_ee[i2]), __fmul_rn(2.0f, a2));
        if (d2 < d1 || (d2 == d1 && i2 < i1)) i1 = i2;
    }
    g_idx[row]   = i1;
    out_idx[row] = (float)i1;
    atomicAdd(&g_cnt[i1], 1);
}

// ---------------------------------------------------------------------------
// K3: fp16 HMMA GEMM + fused argmin. 512 CTAs x 256 thr (8 warps x 16 rows).
// A (128x256 fp16, swizzled) resident in SMEM; B streamed in 16 chunks of 64
// codes, double-buffered via cp.async.
// ---------------------------------------------------------------------------
__global__ __launch_bounds__(GT, 1) void k_gemm(
    const float* __restrict__ z, const float* __restrict__ e,
    float* __restrict__ out_idx)
{
    extern __shared__ char dsm[];
    __shared__ float ee_s[KCODES];

    const uint32_t sA = smem_u32(dsm);          // 65536 B
    const uint32_t sB = sA + 65536;             // 2 x 32768 B
    const int tid = threadIdx.x, wid = tid >> 5, lane = tid & 31;
    const int n0 = blockIdx.x * BM;

    for (int i = tid; i < KCODES; i += GT) ee_s[i] = g_ee[i];

    // preload A tile (128 rows x 32 16B-units, XOR swizzle on unit index)
    const char* gA = (const char*)g_zf16 + (size_t)n0 * 512;
    #pragma unroll
    for (int it = 0; it < 16; it++) {
        int i = it * GT + tid, r = i >> 5, u = i & 31;
        cp16(sA + r * 512 + ((u ^ (r & 7)) << 4), gA + (size_t)r * 512 + u * 16);
    }
    // preload B chunk 0
    const char* gB = (const char*)g_ef16;
    #pragma unroll
    for (int it = 0; it < 8; it++) {
        int i = it * GT + tid, r = i >> 5, u = i & 31;
        cp16(sB + r * 512 + ((u ^ (r & 7)) << 4), gB + (size_t)r * 512 + u * 16);
    }
    CP_COMMIT();
    CP_WAIT0();
    __syncthreads();

    // per-warp / per-lane geometry
    const int wr0 = wid * 16;
    const int rowA = n0 + wr0 + (lane >> 2);          // rows rowA, rowA+8
    const float zzA = g_zz[rowA], zzB = g_zz[rowA + 8];

    // ldmatrix A: lanes 0-15 -> rows, lanes 16-31 -> k+8 halves
    const int amr = wr0 + (lane & 15);
    const uint32_t aBase = sA + amr * 512;
    const int arx = amr & 7;
    const int aku = (lane >> 4) & 1;                  // +1 unit (8 fp16) when lane>=16
    // ldmatrix B (non-trans): n = (lane&7) + 8*(lane&16!=0), k+8 when lane&8
    const int bnl = (lane & 7) + ((lane & 16) ? 8 : 0);
    const int bku = (lane >> 3) & 1;
    uint32_t bOff[4];
    int brx[4];
    #pragma unroll
    for (int np = 0; np < 4; np++) {
        int br = np * 16 + bnl;
        bOff[np] = (uint32_t)br * 512;
        brx[np] = br & 7;
    }

    float v1a = INFINITY, v2a = INFINITY, v1b = INFINITY, v2b = INFINITY;
    int   i1a = 0, i2a = 0, i1b = 0, i2b = 0;

    for (int cc = 0; cc < NCHUNKS; cc++) {
        const uint32_t curB = sB + (cc & 1) * 32768;
        if (cc < NCHUNKS - 1) {
            const char* src = gB + (size_t)(cc + 1) * BNC * 512;
            const uint32_t dstB = sB + ((cc + 1) & 1) * 32768;
            #pragma unroll
            for (int it = 0; it < 8; it++) {
                int i = it * GT + tid, r = i >> 5, u = i & 31;
                cp16(dstB + r * 512 + ((u ^ (r & 7)) << 4),
                     src + (size_t)r * 512 + u * 16);
            }
            CP_COMMIT();
        }

        float c[8][4];
        #pragma unroll
        for (int nt = 0; nt < 8; nt++)
            #pragma unroll
            for (int q = 0; q < 4; q++) c[nt][q] = 0.0f;

        #pragma unroll
        for (int ks = 0; ks < 16; ks++) {
            uint32_t a0, a1, a2, a3;
            uint32_t au = (uint32_t)(ks * 2 + aku);
            ldsm4(a0, a1, a2, a3, aBase + ((au ^ (uint32_t)arx) << 4));
            uint32_t bm[4][4];
            uint32_t bu = (uint32_t)(ks * 2 + bku);
            #pragma unroll
            for (int np = 0; np < 4; np++)
                ldsm4(bm[np][0], bm[np][1], bm[np][2], bm[np][3],
                      curB + bOff[np] + ((bu ^ (uint32_t)brx[np]) << 4));
            #pragma unroll
            for (int nt = 0; nt < 8; nt++)
                mma16816(c[nt], a0, a1, a2, a3,
                         bm[nt >> 1][(nt & 1) * 2], bm[nt >> 1][(nt & 1) * 2 + 1]);
        }

        // fused argmin epilogue: d = fl(fl(zz+ee) - fl(2*acc)), top-2 tracking
        #pragma unroll
        for (int nt = 0; nt < 8; nt++) {
            int code0 = cc * BNC + nt * 8 + ((lane & 3) << 1);
            float e0 = ee_s[code0], e1 = ee_s[code0 + 1];
            float d;
            d = __fsub_rn(__fadd_rn(zzA, e0), __fmul_rn(2.0f, c[nt][0]));
            UPD(v1a, i1a, v2a, i2a, d, code0);
            d = __fsub_rn(__fadd_rn(zzA, e1), __fmul_rn(2.0f, c[nt][1]));
            UPD(v1a, i1a, v2a, i2a, d, code0 + 1);
            d = __fsub_rn(__fadd_rn(zzB, e0), __fmul_rn(2.0f, c[nt][2]));
            UPD(v1b, i1b, v2b, i2b, d, code0);
            d = __fsub_rn(__fadd_rn(zzB, e1), __fmul_rn(2.0f, c[nt][3]));
            UPD(v1b, i1b, v2b, i2b, d, code0 + 1);
        }

        if (cc < NCHUNKS - 1) CP_WAIT0();
        __syncthreads();
    }

    // merge top-2 across the 4 lanes of each quad (same rows, disjoint cols)
    merge_quad(v1a, i1a, v2a, i2a);
    merge_quad(v1b, i1b, v2b, i2b);
    if ((lane & 3) == 0) {
        finalize_row(rowA,     v1a, i1a, v2a, i2a, zzA, z, e, out_idx);
        finalize_row(rowA + 8, v1b, i1b, v2b, i2b, zzB, z, e, out_idx);
    }
}

// ---------------------------------------------------------------------------
// K4: codebook scatter + loss (verified in R1)
// ---------------------------------------------------------------------------
__global__ void k_scatter(const float* __restrict__ z, const float* __restrict__ e,
                          float* __restrict__ out_zq) {
    __shared__ int    sid[128];
    __shared__ double sred[256];
    const int tid = threadIdx.x;
    const int n0 = blockIdx.x * 128;
    const int b = n0 >> 12, hw0 = n0 & 4095;
    if (tid < 128) sid[tid] = g_idx[n0 + tid];
    __syncthreads();
    const int m = tid & 127, cg = tid >> 7;
    const float* zbase = z      + (size_t)b * (CDIM * HW) + hw0 + m;
    float*       obase = out_zq + (size_t)b * (CDIM * HW) + hw0 + m;
    const float* erow  = e + (size_t)sid[m] * CDIM;
    double s = 0.0;
    for (int cc = 0; cc < 128; cc++) {
        int c = cg + 2 * cc;
        float zv = zbase[(size_t)c * HW];
        float df = __fsub_rn(erow[c], zv);
        obase[(size_t)c * HW] = __fadd_rn(zv, df);
        s += (double)df * (double)df;
    }
    sred[tid] = s;
    __syncthreads();
    #pragma unroll
    for (int off = 128; off; off >>= 1) {
        if (tid < off) sred[tid] += sred[tid + off];
        __syncthreads();
    }
    if (tid == 0) atomicAdd(&g_loss, sred[0]);
}

__global__ void k_final(float* __restrict__ out) {
    __shared__ float sred[KCODES];
    int t = threadIdx.x;
    float p = (float)g_cnt[t] * (1.0f / 65536.0f);
    sred[t] = p * logf(p + 1e-10f);
    __syncthreads();
    #pragma unroll
    for (int off = 512; off; off >>= 1) {
        if (t < off) sred[t] += sred[t + off];
        __syncthreads();
    }
    if (t == 0) {
        out[0]        = (float)(g_loss * (1.25 / 16777216.0));
        out[OFF_PERP] = expf(-sred[0]);
    }
}

// ---------------------------------------------------------------------------
extern "C" void kernel_launch(void* const* d_in, const int* in_sizes, int n_in,
                              void* d_out, int out_size) {
    const float* z = (const float*)d_in[0];
    const float* e = (const float*)d_in[1];
    if (n_in >= 2 && in_sizes[0] < in_sizes[1]) {
        z = (const float*)d_in[1];
        e = (const float*)d_in[0];
    }
    float* out = (float*)d_out;

    static int smem_set = 0;
    if (!smem_set) {
        cudaFuncSetAttribute(k_gemm, cudaFuncAttributeMaxDynamicSharedMemorySize, 131072);
        smem_set = 1;
    }

    k_prep   <<<4,   256>>>(e);
    k_conv   <<<256, 256>>>(z);
    k_gemm   <<<512, GT, 131072>>>(z, e, out + OFF_IDX);
    k_scatter<<<512, 256>>>(z, e, out + OFF_ZQ);
    k_final  <<<1,  KCODES>>>(out);
}

// round 6
// speedup vs baseline: 2.5245x; 1.3087x over previous
#include <cuda_runtime.h>
#include <cuda_fp16.h>
#include <math.h>
#include <stdint.h>

#define N_ROWS  65536
#define CDIM    256
#define KCODES  1024
#define HW      4096

#define OFF_ZQ   1
#define OFF_IDX  (1 + 16777216)
#define OFF_PERP (1 + 16777216 + 65536)

#define GT 256            // gemm threads
#define BM 128            // rows per CTA
#define BNC 32            // codes per chunk
#define NCHUNKS 32
#define B_CHUNK_B 16384   // 32 codes x 512 B

// fp16 operand mirrors
__device__ __align__(16) __half g_zf16[(size_t)N_ROWS * CDIM];
__device__ __align__(16) __half g_ef16[(size_t)KCODES * CDIM];
__device__ float  g_zz[N_ROWS];
__device__ float  g_ee[KCODES];
__device__ int    g_idx[N_ROWS];
__device__ int    g_cnt[KCODES];
__device__ double g_loss;

// ---------------- PTX helpers (baseline ISA only) ----------------
__device__ __forceinline__ uint32_t smem_u32(const void* p) {
    uint32_t a;
    asm("{ .reg .u64 t; cvta.to.shared.u64 t, %1; cvt.u32.u64 %0, t; }" : "=r"(a) : "l"(p));
    return a;
}
__device__ __forceinline__ void cp16(uint32_t dst, const void* src) {
    asm volatile("cp.async.cg.shared.global [%0], [%1], 16;" :: "r"(dst), "l"(src));
}
#define CP_COMMIT() asm volatile("cp.async.commit_group;" ::: "memory")
#define CP_WAIT0()  asm volatile("cp.async.wait_group 0;" ::: "memory")

__device__ __forceinline__ void ldsm4(uint32_t& r0, uint32_t& r1, uint32_t& r2,
                                      uint32_t& r3, uint32_t addr) {
    asm volatile("ldmatrix.sync.aligned.m8n8.x4.shared.b16 {%0,%1,%2,%3}, [%4];"
                 : "=r"(r0), "=r"(r1), "=r"(r2), "=r"(r3) : "r"(addr));
}
__device__ __forceinline__ void mma16816(float* c, uint32_t a0, uint32_t a1,
                                         uint32_t a2, uint32_t a3,
                                         uint32_t b0, uint32_t b1) {
    asm volatile(
        "mma.sync.aligned.m16n8k16.row.col.f32.f16.f16.f32 "
        "{%0,%1,%2,%3}, {%4,%5,%6,%7}, {%8,%9}, {%0,%1,%2,%3};"
        : "+f"(c[0]), "+f"(c[1]), "+f"(c[2]), "+f"(c[3])
        : "r"(a0), "r"(a1), "r"(a2), "r"(a3), "r"(b0), "r"(b1));
}

// ---------------------------------------------------------------------------
// K1: e -> fp16 mirror + ee (double), zero counters. grid 4 x 256.
// ---------------------------------------------------------------------------
__global__ void k_prep(const float* __restrict__ e) {
    const int code = blockIdx.x * 256 + threadIdx.x;
    const float* er = e + (size_t)code * CDIM;
    __half* hr = g_ef16 + (size_t)code * CDIM;
    double s = 0.0;
    for (int c8 = 0; c8 < CDIM; c8 += 8) {
        float v[8];
        *(float4*)&v[0] = *(const float4*)(er + c8);
        *(float4*)&v[4] = *(const float4*)(er + c8 + 4);
        __half2 h[4];
        #pragma unroll
        for (int i = 0; i < 4; i++) h[i] = __floats2half2_rn(v[2*i], v[2*i+1]);
        *(uint4*)(hr + c8) = *(uint4*)h;
        #pragma unroll
        for (int i = 0; i < 8; i++) s += (double)v[i] * (double)v[i];
    }
    g_ee[code]  = (float)s;
    g_cnt[code] = 0;
    if (code == 0) g_loss = 0.0;
}

// ---------------------------------------------------------------------------
// K2: z -> fp16 [n][c] + zz, SMEM-staged for coalesced fp16 writes.
// grid 1024 x 256; block handles 64 rows x 256 channels.
// SMEM row stride 258 halves (516B): bank-conflict-free; all SMEM accesses
// are 2B stores / 4B loads (alignment-safe).
// ---------------------------------------------------------------------------
__global__ __launch_bounds__(256) void k_conv(const float* __restrict__ z) {
    __shared__ __half st[64 * 258];
    __shared__ double sdz[64][4];

    const int tid = threadIdx.x;
    const int n0 = blockIdx.x * 64;
    const int b = n0 >> 12, hw0 = n0 & 4095;
    const float* zb = z + (size_t)b * (CDIM * HW) + hw0;

    const int hw = tid & 63;
    const int cq = tid >> 6;             // 0..3
    double s = 0.0;
    #pragma unroll
    for (int k = 0; k < 64; k++) {
        int c = cq + 4 * k;
        float v = zb[(size_t)c * HW + hw];
        st[hw * 258 + c] = __float2half_rn(v);
        s += (double)v * (double)v;
    }
    sdz[hw][cq] = s;
    __syncthreads();

    // coalesced fp16 writes: 4B per lane -> 128B per warp-store, 4 per row
    const int wid = tid >> 5, lane = tid & 31;
    #pragma unroll
    for (int r = 0; r < 8; r++) {
        int row = wid * 8 + r;
        #pragma unroll
        for (int q = 0; q < 4; q++) {
            uint32_t v = *(uint32_t*)&st[row * 258 + q * 64 + lane * 2];
            *(uint32_t*)(g_zf16 + (size_t)(n0 + row) * CDIM + q * 64 + lane * 2) = v;
        }
    }
    if (tid < 64)
        g_zz[n0 + tid] = (float)(sdz[tid][0] + sdz[tid][1] + sdz[tid][2] + sdz[tid][3]);
}

// ---------------------------------------------------------------------------
// top-2 helpers
// ---------------------------------------------------------------------------
#define UPD(v1, i1, v2, i2, d, cd) do { \
    if ((d) < (v1) || ((d) == (v1) && (cd) < (i1))) { \
        (v2) = (v1); (i2) = (i1); (v1) = (d); (i1) = (cd); \
    } else if ((d) < (v2) || ((d) == (v2) && (cd) < (i2))) { \
        (v2) = (d); (i2) = (cd); \
    } } while (0)

__device__ __forceinline__ void merge_quad(float& v1, int& i1, float& v2, int& i2) {
    #pragma unroll
    for (int m = 1; m <= 2; m <<= 1) {
        float w1 = __shfl_xor_sync(0xffffffffu, v1, m);
        int   j1 = __shfl_xor_sync(0xffffffffu, i1, m);
        float w2 = __shfl_xor_sync(0xffffffffu, v2, m);
        int   j2 = __shfl_xor_sync(0xffffffffu, i2, m);
        if (w1 < v1 || (w1 == v1 && j1 < i1)) {
            v2 = v1; i2 = i1; v1 = w1; i1 = j1;
            if (w2 < v2 || (w2 == v2 && j2 < i2)) { v2 = w2; i2 = j2; }
        } else if (w1 < v2 || (w1 == v2 && j1 < i2)) {
            v2 = w1; i2 = j1;
        }
    }
}

__device__ __forceinline__ void finalize_row(int row, float v1, int i1,
                                             float v2, int i2, float zzv,
                                             const float* __restrict__ z,
                                             const float* __restrict__ e,
                                             float* __restrict__ out_idx) {
    if (v2 - v1 < 1e-4f) {
        const float* zr = z + (size_t)(row >> 12) * (CDIM * HW) + (row & 4095);
        const float* e1 = e + (size_t)i1 * CDIM;
        const float* e2 = e + (size_t)i2 * CDIM;
        float a1 = 0.0f, a2 = 0.0f;
        for (int c = 0; c < CDIM; c++) {
            float zv = zr[(size_t)c * HW];
            a1 = fmaf(zv, e1[c], a1);
            a2 = fmaf(zv, e2[c], a2);
        }
        float d1 = __fsub_rn(__fadd_rn(zzv, g_ee[i1]), __fmul_rn(2.0f, a1));
        float d2 = __fsub_rn(__fadd_rn(zzv, g_ee[i2]), __fmul_rn(2.0f, a2));
        if (d2 < d1 || (d2 == d1 && i2 < i1)) i1 = i2;
    }
    g_idx[row]   = i1;
    out_idx[row] = (float)i1;
    atomicAdd(&g_cnt[i1], 1);
}

// ---------------------------------------------------------------------------
// K3: fp16 HMMA GEMM + fused argmin. 512 CTAs x 256 thr, 2 CTAs/SM (96KB).
// A (128x256 fp16, swizzled) resident; B in 32 chunks of 32 codes,
// double-buffered cp.async.
// ---------------------------------------------------------------------------
__global__ __launch_bounds__(GT, 2) void k_gemm(
    const float* __restrict__ z, const float* __restrict__ e,
    float* __restrict__ out_idx)
{
    extern __shared__ char dsm[];
    __shared__ float ee_s[KCODES];

    const uint32_t sA = smem_u32(dsm);          // 65536 B
    const uint32_t sB = sA + 65536;             // 2 x 16384 B
    const int tid = threadIdx.x, wid = tid >> 5, lane = tid & 31;
    const int n0 = blockIdx.x * BM;

    for (int i = tid; i < KCODES; i += GT) ee_s[i] = g_ee[i];

    // preload A tile (128 rows x 32 16B-units, XOR swizzle on unit index)
    const char* gA = (const char*)g_zf16 + (size_t)n0 * 512;
    #pragma unroll
    for (int it = 0; it < 16; it++) {
        int i = it * GT + tid, r = i >> 5, u = i & 31;
        cp16(sA + r * 512 + ((u ^ (r & 7)) << 4), gA + (size_t)r * 512 + u * 16);
    }
    // preload B chunk 0 (32 codes x 512B)
    const char* gB = (const char*)g_ef16;
    #pragma unroll
    for (int it = 0; it < 4; it++) {
        int i = it * GT + tid, r = i >> 5, u = i & 31;
        cp16(sB + r * 512 + ((u ^ (r & 7)) << 4), gB + (size_t)r * 512 + u * 16);
    }
    CP_COMMIT();
    CP_WAIT0();
    __syncthreads();

    // per-warp / per-lane geometry
    const int wr0 = wid * 16;
    const int rowA = n0 + wr0 + (lane >> 2);          // rows rowA, rowA+8
    const float zzA = g_zz[rowA], zzB = g_zz[rowA + 8];

    const int amr = wr0 + (lane & 15);
    const uint32_t aBase = sA + amr * 512;
    const int arx = amr & 7;
    const int aku = (lane >> 4) & 1;
    const int bnl = (lane & 7) + ((lane & 16) ? 8 : 0);
    const int bku = (lane >> 3) & 1;
    const int brx = bnl & 7;
    uint32_t bOff[2];
    #pragma unroll
    for (int np = 0; np < 2; np++)
        bOff[np] = (uint32_t)(np * 16 + bnl) * 512;

    float v1a = INFINITY, v2a = INFINITY, v1b = INFINITY, v2b = INFINITY;
    int   i1a = 0, i2a = 0, i1b = 0, i2b = 0;

    for (int cc = 0; cc < NCHUNKS; cc++) {
        const uint32_t curB = sB + (cc & 1) * B_CHUNK_B;
        if (cc < NCHUNKS - 1) {
            const char* src = gB + (size_t)(cc + 1) * B_CHUNK_B;
            const uint32_t dstB = sB + ((cc + 1) & 1) * B_CHUNK_B;
            #pragma unroll
            for (int it = 0; it < 4; it++) {
                int i = it * GT + tid, r = i >> 5, u = i & 31;
                cp16(dstB + r * 512 + ((u ^ (r & 7)) << 4),
                     src + (size_t)r * 512 + u * 16);
            }
            CP_COMMIT();
        }

        float c[4][4];
        #pragma unroll
        for (int nt = 0; nt < 4; nt++)
            #pragma unroll
            for (int q = 0; q < 4; q++) c[nt][q] = 0.0f;

        #pragma unroll
        for (int ks = 0; ks < 16; ks++) {
            uint32_t a0, a1, a2, a3;
            uint32_t au = (uint32_t)(ks * 2 + aku);
            ldsm4(a0, a1, a2, a3, aBase + ((au ^ (uint32_t)arx) << 4));
            uint32_t bm[2][4];
            uint32_t bu = (uint32_t)(ks * 2 + bku);
            #pragma unroll
            for (int np = 0; np < 2; np++)
                ldsm4(bm[np][0], bm[np][1], bm[np][2], bm[np][3],
                      curB + bOff[np] + ((bu ^ (uint32_t)brx) << 4));
            #pragma unroll
            for (int nt = 0; nt < 4; nt++)
                mma16816(c[nt], a0, a1, a2, a3,
                         bm[nt >> 1][(nt & 1) * 2], bm[nt >> 1][(nt & 1) * 2 + 1]);
        }

        #pragma unroll
        for (int nt = 0; nt < 4; nt++) {
            int code0 = cc * BNC + nt * 8 + ((lane & 3) << 1);
            float e0 = ee_s[code0], e1 = ee_s[code0 + 1];
            float d;
            d = __fsub_rn(__fadd_rn(zzA, e0), __fmul_rn(2.0f, c[nt][0]));
            UPD(v1a, i1a, v2a, i2a, d, code0);
            d = __fsub_rn(__fadd_rn(zzA, e1), __fmul_rn(2.0f, c[nt][1]));
            UPD(v1a, i1a, v2a, i2a, d, code0 + 1);
            d = __fsub_rn(__fadd_rn(zzB, e0), __fmul_rn(2.0f, c[nt][2]));
            UPD(v1b, i1b, v2b, i2b, d, code0);
            d = __fsub_rn(__fadd_rn(zzB, e1), __fmul_rn(2.0f, c[nt][3]));
            UPD(v1b, i1b, v2b, i2b, d, code0 + 1);
        }

        if (cc < NCHUNKS - 1) CP_WAIT0();
        __syncthreads();
    }

    merge_quad(v1a, i1a, v2a, i2a);
    merge_quad(v1b, i1b, v2b, i2b);
    if ((lane & 3) == 0) {
        finalize_row(rowA,     v1a, i1a, v2a, i2a, zzA, z, e, out_idx);
        finalize_row(rowA + 8, v1b, i1b, v2b, i2b, zzB, z, e, out_idx);
    }
}

// ---------------------------------------------------------------------------
// K4: codebook scatter + loss. Thread owns (row m, half the channels):
// e loads are float4 (full line utilization), z/out stay coalesced across m.
// ---------------------------------------------------------------------------
__global__ void k_scatter(const float* __restrict__ z, const float* __restrict__ e,
                          float* __restrict__ out_zq) {
    __shared__ int    sid[128];
    __shared__ double sred[256];
    const int tid = threadIdx.x;
    const int n0 = blockIdx.x * 128;
    const int b = n0 >> 12, hw0 = n0 & 4095;
    if (tid < 128) sid[tid] = g_idx[n0 + tid];
    __syncthreads();
    const int m = tid & 127, half = tid >> 7;
    const int cbase = half * 128;
    const float* zbase = z      + (size_t)b * (CDIM * HW) + hw0 + m + (size_t)cbase * HW;
    float*       obase = out_zq + (size_t)b * (CDIM * HW) + hw0 + m + (size_t)cbase * HW;
    const float* erow  = e + (size_t)sid[m] * CDIM + cbase;

    double s = 0.0;
    #pragma unroll 4
    for (int j = 0; j < 128; j += 4) {
        float4 ev = *(const float4*)(erow + j);
        float evv[4] = {ev.x, ev.y, ev.z, ev.w};
        #pragma unroll
        for (int i = 0; i < 4; i++) {
            float zv = zbase[(size_t)(j + i) * HW];
            float df = __fsub_rn(evv[i], zv);
            obase[(size_t)(j + i) * HW] = __fadd_rn(zv, df);
            s += (double)df * (double)df;
        }
    }
    sred[tid] = s;
    __syncthreads();
    #pragma unroll
    for (int off = 128; off; off >>= 1) {
        if (tid < off) sred[tid] += sred[tid + off];
        __syncthreads();
    }
    if (tid == 0) atomicAdd(&g_loss, sred[0]);
}

__global__ void k_final(float* __restrict__ out) {
    __shared__ float sred[KCODES];
    int t = threadIdx.x;
    float p = (float)g_cnt[t] * (1.0f / 65536.0f);
    sred[t] = p * logf(p + 1e-10f);
    __syncthreads();
    #pragma unroll
    for (int off = 512; off; off >>= 1) {
        if (t < off) sred[t] += sred[t + off];
        __syncthreads();
    }
    if (t == 0) {
        out[0]        = (float)(g_loss * (1.25 / 16777216.0));
        out[OFF_PERP] = expf(-sred[0]);
    }
}

// ---------------------------------------------------------------------------
extern "C" void kernel_launch(void* const* d_in, const int* in_sizes, int n_in,
                              void* d_out, int out_size) {
    const float* z = (const float*)d_in[0];
    const float* e = (const float*)d_in[1];
    if (n_in >= 2 && in_sizes[0] < in_sizes[1]) {
        z = (const float*)d_in[1];
        e = (const float*)d_in[0];
    }
    float* out = (float*)d_out;

    static int smem_set = 0;
    if (!smem_set) {
        cudaFuncSetAttribute(k_gemm, cudaFuncAttributeMaxDynamicSharedMemorySize, 98304);
        smem_set = 1;
    }

    k_prep   <<<4,    256>>>(e);
    k_conv   <<<1024, 256>>>(z);
    k_gemm   <<<512,  GT, 98304>>>(z, e, out + OFF_IDX);
    k_scatter<<<512,  256>>>(z, e, out + OFF_ZQ);
    k_final  <<<1,   KCODES>>>(out);
}

// round 7
// speedup vs baseline: 2.9671x; 1.1753x over previous
#include <cuda_runtime.h>
#include <cuda_fp16.h>
#include <math.h>
#include <stdint.h>

#define N_ROWS  65536
#define CDIM    256
#define KCODES  1024
#define HW      4096

#define OFF_ZQ   1
#define OFF_IDX  (1 + 16777216)
#define OFF_PERP (1 + 16777216 + 65536)

#define GT 128            // gemm threads (4 warps)
#define BM 64             // rows per CTA
#define BNC 32            // codes per chunk
#define NCHUNKS 32
#define B_CHUNK_B 16384   // 32 codes x 512 B
#define GEMM_DYN 65536    // 32KB A + 2x16KB B

// fp16 operand mirrors
__device__ __align__(16) __half g_zf16[(size_t)N_ROWS * CDIM];
__device__ __align__(16) __half g_ef16[(size_t)KCODES * CDIM];
__device__ float  g_zz[N_ROWS];
__device__ float  g_ee[KCODES];
__device__ int    g_idx[N_ROWS];
__device__ int    g_cnt[KCODES];
__device__ double g_loss;

// ---------------- PTX helpers (baseline ISA only) ----------------
__device__ __forceinline__ uint32_t smem_u32(const void* p) {
    uint32_t a;
    asm("{ .reg .u64 t; cvta.to.shared.u64 t, %1; cvt.u32.u64 %0, t; }" : "=r"(a) : "l"(p));
    return a;
}
__device__ __forceinline__ void cp16(uint32_t dst, const void* src) {
    asm volatile("cp.async.cg.shared.global [%0], [%1], 16;" :: "r"(dst), "l"(src));
}
#define CP_COMMIT() asm volatile("cp.async.commit_group;" ::: "memory")
#define CP_WAIT0()  asm volatile("cp.async.wait_group 0;" ::: "memory")

__device__ __forceinline__ void ldsm4(uint32_t& r0, uint32_t& r1, uint32_t& r2,
                                      uint32_t& r3, uint32_t addr) {
    asm volatile("ldmatrix.sync.aligned.m8n8.x4.shared.b16 {%0,%1,%2,%3}, [%4];"
                 : "=r"(r0), "=r"(r1), "=r"(r2), "=r"(r3) : "r"(addr));
}
__device__ __forceinline__ void mma16816(float* c, uint32_t a0, uint32_t a1,
                                         uint32_t a2, uint32_t a3,
                                         uint32_t b0, uint32_t b1) {
    asm volatile(
        "mma.sync.aligned.m16n8k16.row.col.f32.f16.f16.f32 "
        "{%0,%1,%2,%3}, {%4,%5,%6,%7}, {%8,%9}, {%0,%1,%2,%3};"
        : "+f"(c[0]), "+f"(c[1]), "+f"(c[2]), "+f"(c[3])
        : "r"(a0), "r"(a1), "r"(a2), "r"(a3), "r"(b0), "r"(b1));
}

// ---------------------------------------------------------------------------
// K1: e -> fp16 mirror + ee (double), zero counters. grid 4 x 256.
// ---------------------------------------------------------------------------
__global__ void k_prep(const float* __restrict__ e) {
    const int code = blockIdx.x * 256 + threadIdx.x;
    const float* er = e + (size_t)code * CDIM;
    __half* hr = g_ef16 + (size_t)code * CDIM;
    double s = 0.0;
    for (int c8 = 0; c8 < CDIM; c8 += 8) {
        float v[8];
        *(float4*)&v[0] = *(const float4*)(er + c8);
        *(float4*)&v[4] = *(const float4*)(er + c8 + 4);
        __half2 h[4];
        #pragma unroll
        for (int i = 0; i < 4; i++) h[i] = __floats2half2_rn(v[2*i], v[2*i+1]);
        *(uint4*)(hr + c8) = *(uint4*)h;
        #pragma unroll
        for (int i = 0; i < 8; i++) s += (double)v[i] * (double)v[i];
    }
    g_ee[code]  = (float)s;
    g_cnt[code] = 0;
    if (code == 0) g_loss = 0.0;
}

// ---------------------------------------------------------------------------
// K2: z -> fp16 [n][c] + zz (fp32 accum — argmin is invariant to zz offsets),
// SMEM-staged for coalesced fp16 writes. grid 1024 x 256.
// ---------------------------------------------------------------------------
__global__ __launch_bounds__(256) void k_conv(const float* __restrict__ z) {
    __shared__ __half st[64 * 258];
    __shared__ float sdz[64][4];

    const int tid = threadIdx.x;
    const int n0 = blockIdx.x * 64;
    const int b = n0 >> 12, hw0 = n0 & 4095;
    const float* zb = z + (size_t)b * (CDIM * HW) + hw0;

    const int hw = tid & 63;
    const int cq = tid >> 6;             // 0..3
    float s = 0.0f;
    #pragma unroll
    for (int k = 0; k < 64; k++) {
        int c = cq + 4 * k;
        float v = zb[(size_t)c * HW + hw];
        st[hw * 258 + c] = __float2half_rn(v);
        s = fmaf(v, v, s);
    }
    sdz[hw][cq] = s;
    __syncthreads();

    const int wid = tid >> 5, lane = tid & 31;
    #pragma unroll
    for (int r = 0; r < 8; r++) {
        int row = wid * 8 + r;
        #pragma unroll
        for (int q = 0; q < 4; q++) {
            uint32_t v = *(uint32_t*)&st[row * 258 + q * 64 + lane * 2];
            *(uint32_t*)(g_zf16 + (size_t)(n0 + row) * CDIM + q * 64 + lane * 2) = v;
        }
    }
    if (tid < 64)
        g_zz[n0 + tid] = sdz[tid][0] + sdz[tid][1] + sdz[tid][2] + sdz[tid][3];
}

// ---------------------------------------------------------------------------
// top-2 helpers
// ---------------------------------------------------------------------------
#define UPD(v1, i1, v2, i2, d, cd) do { \
    if ((d) < (v1) || ((d) == (v1) && (cd) < (i1))) { \
        (v2) = (v1); (i2) = (i1); (v1) = (d); (i1) = (cd); \
    } else if ((d) < (v2) || ((d) == (v2) && (cd) < (i2))) { \
        (v2) = (d); (i2) = (cd); \
    } } while (0)

__device__ __forceinline__ void merge_quad(float& v1, int& i1, float& v2, int& i2) {
    #pragma unroll
    for (int m = 1; m <= 2; m <<= 1) {
        float w1 = __shfl_xor_sync(0xffffffffu, v1, m);
        int   j1 = __shfl_xor_sync(0xffffffffu, i1, m);
        float w2 = __shfl_xor_sync(0xffffffffu, v2, m);
        int   j2 = __shfl_xor_sync(0xffffffffu, i2, m);
        if (w1 < v1 || (w1 == v1 && j1 < i1)) {
            v2 = v1; i2 = i1; v1 = w1; i1 = j1;
            if (w2 < v2 || (w2 == v2 && j2 < i2)) { v2 = w2; i2 = j2; }
        } else if (w1 < v2 || (w1 == v2 && j1 < i2)) {
            v2 = w1; i2 = j1;
        }
    }
}

__device__ __forceinline__ void finalize_row(int row, float v1, int i1,
                                             float v2, int i2, float zzv,
                                             const float* __restrict__ z,
                                             const float* __restrict__ e,
                                             float* __restrict__ out_idx) {
    if (v2 - v1 < 1e-4f) {
        const float* zr = z + (size_t)(row >> 12) * (CDIM * HW) + (row & 4095);
        const float* e1 = e + (size_t)i1 * CDIM;
        const float* e2 = e + (size_t)i2 * CDIM;
        float a1 = 0.0f, a2 = 0.0f;
        for (int c = 0; c < CDIM; c++) {
            float zv = zr[(size_t)c * HW];
            a1 = fmaf(zv, e1[c], a1);
            a2 = fmaf(zv, e2[c], a2);
        }
        float d1 = __fsub_rn(__fadd_rn(zzv, g_ee[i1]), __fmul_rn(2.0f, a1));
        float d2 = __fsub_rn(__fadd_rn(zzv, g_ee[i2]), __fmul_rn(2.0f, a2));
        if (d2 < d1 || (d2 == d1 && i2 < i1)) i1 = i2;
    }
    g_idx[row]   = i1;
    out_idx[row] = (float)i1;
    atomicAdd(&g_cnt[i1], 1);
}

// ---------------------------------------------------------------------------
// K3: fp16 HMMA GEMM + fused argmin. 1024 CTAs x 128 thr, 3 CTAs/SM (64KB dyn).
// A (64x256 fp16, swizzled) resident; B in 32 chunks of 32 codes,
// double-buffered cp.async. Per-warp tile: 16 rows x 32 codes.
// ---------------------------------------------------------------------------
__global__ __launch_bounds__(GT, 3) void k_gemm(
    const float* __restrict__ z, const float* __restrict__ e,
    float* __restrict__ out_idx)
{
    extern __shared__ char dsm[];
    __shared__ float ee_s[KCODES];

    const uint32_t sA = smem_u32(dsm);          // 32768 B
    const uint32_t sB = sA + 32768;             // 2 x 16384 B
    const int tid = threadIdx.x, wid = tid >> 5, lane = tid & 31;
    const int n0 = blockIdx.x * BM;

    for (int i = tid; i < KCODES; i += GT) ee_s[i] = g_ee[i];

    // preload A tile (64 rows x 32 16B-units, XOR swizzle on unit index)
    const char* gA = (const char*)g_zf16 + (size_t)n0 * 512;
    #pragma unroll
    for (int it = 0; it < 16; it++) {
        int i = it * GT + tid, r = i >> 5, u = i & 31;
        cp16(sA + r * 512 + ((u ^ (r & 7)) << 4), gA + (size_t)r * 512 + u * 16);
    }
    // preload B chunk 0 (32 codes x 512B)
    const char* gB = (const char*)g_ef16;
    #pragma unroll
    for (int it = 0; it < 8; it++) {
        int i = it * GT + tid, r = i >> 5, u = i & 31;
        cp16(sB + r * 512 + ((u ^ (r & 7)) << 4), gB + (size_t)r * 512 + u * 16);
    }
    CP_COMMIT();
    CP_WAIT0();
    __syncthreads();

    // per-warp / per-lane geometry (warp owns rows wid*16 .. wid*16+15)
    const int wr0 = wid * 16;
    const int rowA = n0 + wr0 + (lane >> 2);          // rows rowA, rowA+8
    const float zzA = g_zz[rowA], zzB = g_zz[rowA + 8];

    const int amr = wr0 + (lane & 15);
    const uint32_t aBase = sA + amr * 512;
    const int arx = amr & 7;
    const int aku = (lane >> 4) & 1;
    const int bnl = (lane & 7) + ((lane & 16) ? 8 : 0);
    const int bku = (lane >> 3) & 1;
    const int brx = bnl & 7;
    uint32_t bOff[2];
    #pragma unroll
    for (int np = 0; np < 2; np++)
        bOff[np] = (uint32_t)(np * 16 + bnl) * 512;

    float v1a = INFINITY, v2a = INFINITY, v1b = INFINITY, v2b = INFINITY;
    int   i1a = 0, i2a = 0, i1b = 0, i2b = 0;

    for (int cc = 0; cc < NCHUNKS; cc++) {
        const uint32_t curB = sB + (cc & 1) * B_CHUNK_B;
        if (cc < NCHUNKS - 1) {
            const char* src = gB + (size_t)(cc + 1) * B_CHUNK_B;
            const uint32_t dstB = sB + ((cc + 1) & 1) * B_CHUNK_B;
            #pragma unroll
            for (int it = 0; it < 8; it++) {
                int i = it * GT + tid, r = i >> 5, u = i & 31;
                cp16(dstB + r * 512 + ((u ^ (r & 7)) << 4),
                     src + (size_t)r * 512 + u * 16);
            }
            CP_COMMIT();
        }

        float c[4][4];
        #pragma unroll
        for (int nt = 0; nt < 4; nt++)
            #pragma unroll
            for (int q = 0; q < 4; q++) c[nt][q] = 0.0f;

        #pragma unroll
        for (int ks = 0; ks < 16; ks++) {
            uint32_t a0, a1, a2, a3;
            uint32_t au = (uint32_t)(ks * 2 + aku);
            ldsm4(a0, a1, a2, a3, aBase + ((au ^ (uint32_t)arx) << 4));
            uint32_t bm[2][4];
            uint32_t bu = (uint32_t)(ks * 2 + bku);
            #pragma unroll
            for (int np = 0; np < 2; np++)
                ldsm4(bm[np][0], bm[np][1], bm[np][2], bm[np][3],
                      curB + bOff[np] + ((bu ^ (uint32_t)brx) << 4));
            #pragma unroll
            for (int nt = 0; nt < 4; nt++)
                mma16816(c[nt], a0, a1, a2, a3,
                         bm[nt >> 1][(nt & 1) * 2], bm[nt >> 1][(nt & 1) * 2 + 1]);
        }

        #pragma unroll
        for (int nt = 0; nt < 4; nt++) {
            int code0 = cc * BNC + nt * 8 + ((lane & 3) << 1);
            float e0 = ee_s[code0], e1 = ee_s[code0 + 1];
            float d;
            d = __fsub_rn(__fadd_rn(zzA, e0), __fmul_rn(2.0f, c[nt][0]));
            UPD(v1a, i1a, v2a, i2a, d, code0);
            d = __fsub_rn(__fadd_rn(zzA, e1), __fmul_rn(2.0f, c[nt][1]));
            UPD(v1a, i1a, v2a, i2a, d, code0 + 1);
            d = __fsub_rn(__fadd_rn(zzB, e0), __fmul_rn(2.0f, c[nt][2]));
            UPD(v1b, i1b, v2b, i2b, d, code0);
            d = __fsub_rn(__fadd_rn(zzB, e1), __fmul_rn(2.0f, c[nt][3]));
            UPD(v1b, i1b, v2b, i2b, d, code0 + 1);
        }

        if (cc < NCHUNKS - 1) CP_WAIT0();
        __syncthreads();
    }

    merge_quad(v1a, i1a, v2a, i2a);
    merge_quad(v1b, i1b, v2b, i2b);
    if ((lane & 3) == 0) {
        finalize_row(rowA,     v1a, i1a, v2a, i2a, zzA, z, e, out_idx);
        finalize_row(rowA + 8, v1b, i1b, v2b, i2b, zzB, z, e, out_idx);
    }
}

// ---------------------------------------------------------------------------
// K4: codebook scatter + loss (fp32 accum, double only at the atomic).
// grid 1024 x 256; thread = (row m of 64, quarter q of channels).
// ---------------------------------------------------------------------------
__global__ __launch_bounds__(256) void k_scatter(
    const float* __restrict__ z, const float* __restrict__ e,
    float* __restrict__ out_zq)
{
    __shared__ int   sid[64];
    __shared__ float sred[256];
    const int tid = threadIdx.x;
    const int n0 = blockIdx.x * 64;
    const int b = n0 >> 12, hw0 = n0 & 4095;
    if (tid < 64) sid[tid] = g_idx[n0 + tid];
    __syncthreads();
    const int m = tid & 63, q = tid >> 6;
    const int cbase = q * 64;
    const float* zbase = z      + (size_t)b * (CDIM * HW) + hw0 + m + (size_t)cbase * HW;
    float*       obase = out_zq + (size_t)b * (CDIM * HW) + hw0 + m + (size_t)cbase * HW;
    const float* erow  = e + (size_t)sid[m] * CDIM + cbase;

    float s = 0.0f;
    #pragma unroll 4
    for (int j = 0; j < 64; j += 4) {
        float4 ev = *(const float4*)(erow + j);
        float evv[4] = {ev.x, ev.y, ev.z, ev.w};
        #pragma unroll
        for (int i = 0; i < 4; i++) {
            float zv = zbase[(size_t)(j + i) * HW];
            float df = __fsub_rn(evv[i], zv);
            obase[(size_t)(j + i) * HW] = __fadd_rn(zv, df);
            s = fmaf(df, df, s);
        }
    }
    sred[tid] = s;
    __syncthreads();
    #pragma unroll
    for (int off = 128; off; off >>= 1) {
        if (tid < off) sred[tid] += sred[tid + off];
        __syncthreads();
    }
    if (tid == 0) atomicAdd(&g_loss, (double)sred[0]);
}

__global__ void k_final(float* __restrict__ out) {
    __shared__ float sred[KCODES];
    int t = threadIdx.x;
    float p = (float)g_cnt[t] * (1.0f / 65536.0f);
    sred[t] = p * logf(p + 1e-10f);
    __syncthreads();
    #pragma unroll
    for (int off = 512; off; off >>= 1) {
        if (t < off) sred[t] += sred[t + off];
        __syncthreads();
    }
    if (t == 0) {
        out[0]        = (float)(g_loss * (1.25 / 16777216.0));
        out[OFF_PERP] = expf(-sred[0]);
    }
}

// ---------------------------------------------------------------------------
extern "C" void kernel_launch(void* const* d_in, const int* in_sizes, int n_in,
                              void* d_out, int out_size) {
    const float* z = (const float*)d_in[0];
    const float* e = (const float*)d_in[1];
    if (n_in >= 2 && in_sizes[0] < in_sizes[1]) {
        z = (const float*)d_in[1];
        e = (const float*)d_in[0];
    }
    float* out = (float*)d_out;

    static int smem_set = 0;
    if (!smem_set) {
        cudaFuncSetAttribute(k_gemm, cudaFuncAttributeMaxDynamicSharedMemorySize, GEMM_DYN);
        smem_set = 1;
    }

    k_prep   <<<4,    256>>>(e);
    k_conv   <<<1024, 256>>>(z);
    k_gemm   <<<1024, GT, GEMM_DYN>>>(z, e, out + OFF_IDX);
    k_scatter<<<1024, 256>>>(z, e, out + OFF_ZQ);
    k_final  <<<1,   KCODES>>>(out);
}